// round 1
// baseline (speedup 1.0000x reference)
#include <cuda_runtime.h>

#define D_IN   1024
#define D_FEAT 4096
#define DEG    4
#define RPB    8          // rows per block

// Shared layout (per degree d): word index = d*8192 + i*8 + (r ^ ((i>>2)&7))
//  - transposed STS (fixed r, lanes sweep i = k*32+lane): bank = 8*(lane&3) + (r ^ (lane>>2))
//    -> all 32 banks distinct: conflict-free store.
//  - gather LDS (fixed idx, lanes sweep r=0..7): full distinct 8-bank group keyed by idx&3.
//    Conflicts only between features colliding mod 4 (E[max degree] = 2.125).

__global__ __launch_bounds__(1024, 1)
void srht_kernel(const float* __restrict__ x,
                 const float* __restrict__ rad,
                 const int*   __restrict__ perm,
                 const float* __restrict__ log_ls,
                 const float* __restrict__ log_var,
                 float* __restrict__ out)
{
    extern __shared__ float sw[];   // DEG * D_IN * RPB floats = 128 KB

    const int tid  = threadIdx.x;
    const int wid  = tid >> 5;
    const int lane = tid & 31;
    const int row0 = blockIdx.x * RPB;

    const float inv_ls = expf(-log_ls[0]);

    // ---------- Phase 1: FWHT in registers. Warp -> (degree d, row r). ----------
    {
        const int d = wid >> 3;     // 0..3
        const int r = wid & 7;      // 0..7
        const float* __restrict__ xr = x + (size_t)(row0 + r) * D_IN;
        const float* __restrict__ rd = rad + d * D_IN;

        float v[32];                // lane holds i = k*32 + lane
        #pragma unroll
        for (int k = 0; k < 32; k++) {
            int i = k * 32 + lane;
            v[k] = xr[i] * rd[i] * inv_ls;
        }

        // Butterfly stages on lane bits (h = 1,2,4,8,16) via shuffle.
        // (Hadamard stages commute, so any stage order computes the same transform.)
        #pragma unroll
        for (int hb = 0; hb < 5; hb++) {
            const int h = 1 << hb;
            const bool up = (lane & h) != 0;
            #pragma unroll
            for (int k = 0; k < 32; k++) {
                float o = __shfl_xor_sync(0xffffffffu, v[k], h);
                v[k] = up ? (o - v[k]) : (v[k] + o);
            }
        }
        // Butterfly stages on register bits (h = 32,64,128,256,512).
        #pragma unroll
        for (int mb = 0; mb < 5; mb++) {
            const int m = 1 << mb;
            #pragma unroll
            for (int k = 0; k < 32; k++) {
                if ((k & m) == 0) {
                    float a = v[k];
                    float b = v[k + m];
                    v[k]     = a + b;
                    v[k + m] = a - b;
                }
            }
        }

        // Transposed, swizzled store (conflict-free per the layout note above).
        float* __restrict__ swd = sw + d * (D_IN * RPB);
        #pragma unroll
        for (int k = 0; k < 32; k++) {
            int i = k * 32 + lane;
            swd[i * 8 + (r ^ ((i >> 2) & 7))] = v[k];
        }
    }
    __syncthreads();

    // ---------- Phase 2: permutation gather + product across degrees. ----------
    // Lane layout: r = lane>>2 (row 0..7), c = lane&3 (feature quad).
    // Each thread owns 4 consecutive features -> STG.128.
    const float oscale = expf(0.5f * log_var[0]) * (1.0f / 64.0f);  // / sqrt(4096)
    const int gr = lane >> 2;
    const int gc = lane & 3;
    float* __restrict__ outr = out + (size_t)(row0 + gr) * D_FEAT;

    #pragma unroll
    for (int it = 0; it < 8; it++) {
        const int fb = it * 512 + wid * 16 + gc * 4;   // base feature of this thread's quad
        float acc0 = oscale, acc1 = oscale, acc2 = oscale, acc3 = oscale;
        #pragma unroll
        for (int d = 0; d < DEG; d++) {
            const int* __restrict__ pd = perm + d * D_FEAT + fb;
            const float* __restrict__ swd = sw + d * (D_IN * RPB);
            const int i0 = pd[0], i1 = pd[1], i2 = pd[2], i3 = pd[3];
            acc0 *= swd[i0 * 8 + (gr ^ ((i0 >> 2) & 7))];
            acc1 *= swd[i1 * 8 + (gr ^ ((i1 >> 2) & 7))];
            acc2 *= swd[i2 * 8 + (gr ^ ((i2 >> 2) & 7))];
            acc3 *= swd[i3 * 8 + (gr ^ ((i3 >> 2) & 7))];
        }
        float4 res = make_float4(acc0, acc1, acc2, acc3);
        *reinterpret_cast<float4*>(outr + fb) = res;
    }
}

extern "C" void kernel_launch(void* const* d_in, const int* in_sizes, int n_in,
                              void* d_out, int out_size)
{
    const float* x   = (const float*)d_in[0];
    const float* rad = (const float*)d_in[1];
    const int*   pm  = (const int*)d_in[2];
    const float* lls = (const float*)d_in[3];
    const float* lv  = (const float*)d_in[4];
    float* out = (float*)d_out;

    const int rows = in_sizes[0] / D_IN;          // 16384
    const int smem = DEG * D_IN * RPB * (int)sizeof(float);  // 131072 B

    cudaFuncSetAttribute(srht_kernel,
                         cudaFuncAttributeMaxDynamicSharedMemorySize, smem);
    srht_kernel<<<rows / RPB, 1024, smem>>>(x, rad, pm, lls, lv, out);
}